// round 6
// baseline (speedup 1.0000x reference)
#include <cuda_runtime.h>

#define BN 1024
#define CN 128
#define DN 16
#define SN 4
#define K3C 23
#define K2C 5
#define K1C 2

#define NM3 816   // C(18,3) sorted triples i>=j>=l
#define NM2 136   // C(17,2) sorted pairs  i>=j
#define STREAM_LEN (NM3*4 + NM2*4 + 16*4)  // 3872 floats per (e,c)

// ---------------- scratch ----------------
__device__ float g_us3[NM3 * 4 * K3C];                   // [m3][oc][k]
__device__ float g_us2[NM2 * 4 * K2C];                   // [m2][oc][k]
__device__ float g_stream[(size_t)SN * CN * STREAM_LEN]; // [e][c][3872]
__device__ int   g_sorted[BN];
__device__ int   g_off[SN + 1];
__device__ float g_y[(size_t)BN * CN * 4];               // [b][c][oc]

// ---------------- presym: u3/u2 -> symmetric monomial bases ----------------
// grid 817: blocks 0..815 -> one m3 each (96 thr, 92 active = oc*k);
// block 816 -> all of us2.
__global__ void k_presym(const float* __restrict__ u3_0, const float* __restrict__ u3_1,
                         const float* __restrict__ u2_0, const float* __restrict__ u2_1) {
    const int m = blockIdx.x;
    const int tid = threadIdx.x;
    if (m < NM3) {
        if (tid >= 4 * K3C) return;
        const int oc = tid / K3C, k = tid - oc * K3C;
        int i = 0;
        while ((i + 1) * (i + 2) * (i + 3) / 6 <= m) i++;
        int r = m - i * (i + 1) * (i + 2) / 6;
        int j = 0;
        while ((j + 1) * (j + 2) / 2 <= r) j++;
        int l = r - j * (j + 1) / 2;

        auto val = [&](int a, int b, int d) -> float {
            return (oc == 0) ? u3_0[((a * 16 + b) * 16 + d) * K3C + k]
                             : u3_1[((((oc - 1) * 16 + a) * 16 + b) * 16 + d) * K3C + k];
        };
        float s;
        if (i == j && j == l)      s = val(i, i, i);
        else if (i == j)           s = val(i, i, l) + val(i, l, i) + val(l, i, i);
        else if (j == l)           s = val(i, j, j) + val(j, i, j) + val(j, j, i);
        else                       s = val(i, j, l) + val(i, l, j) + val(j, i, l)
                                     + val(j, l, i) + val(l, i, j) + val(l, j, i);
        g_us3[(m * 4 + oc) * K3C + k] = s;
    } else {
        // us2: 136*4*5 = 2720 elements
        for (int idx = tid; idx < NM2 * 4 * K2C; idx += blockDim.x) {
            int m2 = idx / (4 * K2C);
            int rem = idx - m2 * (4 * K2C);
            int oc = rem / K2C, k = rem - oc * K2C;
            int i = 0;
            while ((i + 1) * (i + 2) / 2 <= m2) i++;
            int j = m2 - i * (i + 1) / 2;
            float s = (oc == 0) ? u2_0[(i * 16 + j) * K2C + k]
                                : u2_1[(((oc - 1) * 16 + i) * 16 + j) * K2C + k];
            if (i != j)
                s += (oc == 0) ? u2_0[(j * 16 + i) * K2C + k]
                               : u2_1[(((oc - 1) * 16 + j) * 16 + i) * K2C + k];
            g_us2[idx] = s;
        }
    }
}

// ---------------- fold: build coefficient streams ----------------
// grid (52, 4): x<51 -> corr3 tile of 16 monomials; x==51 -> corr2 + corr1.
// 256 threads: c = tid&127, h = tid>>7.
__global__ void k_fold(const float* __restrict__ w3, const float* __restrict__ w2,
                       const float* __restrict__ w1,
                       const float* __restrict__ u1_0, const float* __restrict__ u1_1) {
    __shared__ float sA[2 * K3C * 128]; // 5888: w3  (or w2|w1|u1 packed)
    __shared__ float sB[NM2 * 4 * K2C]; // 2720: us3 tile (1472) or us2 (2720)
    const int tid = threadIdx.x;
    const int e = blockIdx.y;
    const int c = tid & 127, h = tid >> 7;
    float* outp = g_stream + ((size_t)(e * 128 + c)) * STREAM_LEN;

    if (blockIdx.x < 51) {
        const int mt = blockIdx.x * 16;
        for (int idx = tid; idx < 2 * K3C * 128; idx += 256) {
            int br = idx / (K3C * 128);
            int rem = idx - br * (K3C * 128);
            int k = rem >> 7, cc = rem & 127;
            sA[idx] = w3[(((size_t)(br * 4 + e) * K3C + k) * 128) + cc];
        }
        for (int idx = tid; idx < 16 * 4 * K3C; idx += 256)
            sB[idx] = g_us3[mt * 4 * K3C + idx];
        __syncthreads();

        for (int mm = h; mm < 16; mm += 2) {
            const float* u0 = sB + (mm * 4 + 0) * K3C;
            const float* u1p = sB + (mm * 4 + 1) * K3C;
            const float* u2p = sB + (mm * 4 + 2) * K3C;
            const float* u3p = sB + (mm * 4 + 3) * K3C;
            float a0 = 0.f, a1 = 0.f, a2 = 0.f, a3 = 0.f;
#pragma unroll
            for (int k = 0; k < K3C; k++) {
                float w0  = sA[k * 128 + c];
                float w1v = sA[K3C * 128 + k * 128 + c];
                a0 = fmaf(u0[k],  w0,  a0);
                a1 = fmaf(u1p[k], w1v, a1);
                a2 = fmaf(u2p[k], w1v, a2);
                a3 = fmaf(u3p[k], w1v, a3);
            }
            *(float4*)(outp + (size_t)(mt + mm) * 4) = make_float4(a0, a1, a2, a3);
        }
    } else {
        // pack: w2 at sA[0,1280), w1 at sA[1280,1792), u1 at sA[1792,1920)
        for (int idx = tid; idx < 2 * K2C * 128; idx += 256) {
            int br = idx / (K2C * 128);
            int rem = idx - br * (K2C * 128);
            int k = rem >> 7, cc = rem & 127;
            sA[idx] = w2[(((size_t)(br * 4 + e) * K2C + k) * 128) + cc];
        }
        for (int idx = tid; idx < 2 * K1C * 128; idx += 256) {
            int br = idx / (K1C * 128);
            int rem = idx - br * (K1C * 128);
            int k = rem >> 7, cc = rem & 127;
            sA[1280 + idx] = w1[(((size_t)(br * 4 + e) * K1C + k) * 128) + cc];
        }
        for (int idx = tid; idx < 4 * 16 * K1C; idx += 256) {
            int oc = idx / (16 * K1C);
            int rem = idx - oc * (16 * K1C);
            int i = rem / K1C, k = rem % K1C;
            sA[1792 + idx] = (oc == 0) ? u1_0[i * K1C + k]
                                       : u1_1[((oc - 1) * 16 + i) * K1C + k];
        }
        for (int idx = tid; idx < NM2 * 4 * K2C; idx += 256)
            sB[idx] = g_us2[idx];
        __syncthreads();

        for (int m = h; m < NM2; m += 2) {
            float a0 = 0.f, a1 = 0.f, a2 = 0.f, a3 = 0.f;
#pragma unroll
            for (int k = 0; k < K2C; k++) {
                float w0  = sA[k * 128 + c];
                float w1v = sA[K2C * 128 + k * 128 + c];
                a0 = fmaf(sB[(m * 4 + 0) * K2C + k], w0,  a0);
                a1 = fmaf(sB[(m * 4 + 1) * K2C + k], w1v, a1);
                a2 = fmaf(sB[(m * 4 + 2) * K2C + k], w1v, a2);
                a3 = fmaf(sB[(m * 4 + 3) * K2C + k], w1v, a3);
            }
            *(float4*)(outp + NM3 * 4 + (size_t)m * 4) = make_float4(a0, a1, a2, a3);
        }
        for (int i = h; i < 16; i += 2) {
            float a0 = 0.f, a1 = 0.f, a2 = 0.f, a3 = 0.f;
#pragma unroll
            for (int k = 0; k < K1C; k++) {
                float w0  = sA[1280 + k * 128 + c];
                float w1v = sA[1280 + K1C * 128 + k * 128 + c];
                a0 = fmaf(sA[1792 + (0 * 16 + i) * K1C + k], w0,  a0);
                a1 = fmaf(sA[1792 + (1 * 16 + i) * K1C + k], w1v, a1);
                a2 = fmaf(sA[1792 + (2 * 16 + i) * K1C + k], w1v, a2);
                a3 = fmaf(sA[1792 + (3 * 16 + i) * K1C + k], w1v, a3);
            }
            *(float4*)(outp + NM3 * 4 + NM2 * 4 + (size_t)i * 4) = make_float4(a0, a1, a2, a3);
        }
    }
}

// ---------------- counting sort by species ----------------
__global__ void k_sort(const int* __restrict__ species) {
    __shared__ int cnt[SN], cur[SN], off[SN + 1];
    const int tid = threadIdx.x; // 1024
    if (tid < SN) { cnt[tid] = 0; cur[tid] = 0; }
    __syncthreads();
    int s = species[tid];
    atomicAdd(&cnt[s], 1);
    __syncthreads();
    if (tid == 0) {
        off[0] = 0;
        for (int e = 0; e < SN; e++) off[e + 1] = off[e] + cnt[e];
        for (int e = 0; e <= SN; e++) g_off[e] = off[e];
    }
    __syncthreads();
    int pos = off[s] + atomicAdd(&cur[s], 1);
    g_sorted[pos] = tid;
}

// ---------------- main: symmetric monomial evaluation ----------------
// grid (c=128, e=4, split=2), 128 threads, 1 node/thread
#define TMS 128
__global__ __launch_bounds__(TMS, 8) void k_main_sym(const float* __restrict__ xg) {
    __shared__ __align__(16) float sC[STREAM_LEN]; // 15.5KB
    const int c = blockIdx.x, e = blockIdx.y, z = blockIdx.z;
    const int tid = threadIdx.x;

    {
        const float4* gs = (const float4*)(g_stream + ((size_t)(e * 128 + c)) * STREAM_LEN);
        float4* s4 = (float4*)sC;
#pragma unroll
        for (int q = 0; q < 8; q++) {
            int idx = tid + q * TMS;
            if (idx < STREAM_LEN / 4) s4[idx] = gs[idx];
        }
    }
    const int lo = g_off[e], hi = g_off[e + 1];
    __syncthreads();

    const float4* p3 = (const float4*)sC;
    const float4* p2 = (const float4*)(sC + NM3 * 4);
    const float4* p1 = (const float4*)(sC + NM3 * 4 + NM2 * 4);

    for (int t = lo + z * TMS + tid; t < hi; t += 2 * TMS) {
        const int b = g_sorted[t];
        float x[16];
        {
            const float4* q0 = (const float4*)(xg + ((size_t)b * 128 + c) * 16);
#pragma unroll
            for (int q = 0; q < 4; q++) {
                float4 a = q0[q];
                x[4 * q + 0] = a.x; x[4 * q + 1] = a.y;
                x[4 * q + 2] = a.z; x[4 * q + 3] = a.w;
            }
        }

        float y0 = 0.f, y1 = 0.f, y2 = 0.f, y3 = 0.f;
        int m3 = 0, m2 = 0;
#pragma unroll
        for (int i = 0; i < 16; i++) {
            {
                const float4 c1 = p1[i];
                const float xi = x[i];
                y0 = fmaf(c1.x, xi, y0);
                y1 = fmaf(c1.y, xi, y1);
                y2 = fmaf(c1.z, xi, y2);
                y3 = fmaf(c1.w, xi, y3);
            }
#pragma unroll
            for (int j = 0; j <= i; j++) {
                const float q = x[i] * x[j];
                {
                    const float4 c2 = p2[m2]; m2++;
                    y0 = fmaf(c2.x, q, y0);
                    y1 = fmaf(c2.y, q, y1);
                    y2 = fmaf(c2.z, q, y2);
                    y3 = fmaf(c2.w, q, y3);
                }
#pragma unroll
                for (int l = 0; l <= j; l++) {
                    const float4 c3 = p3[m3]; m3++;
                    const float tv = q * x[l];
                    y0 = fmaf(c3.x, tv, y0);
                    y1 = fmaf(c3.y, tv, y1);
                    y2 = fmaf(c3.z, tv, y2);
                    y3 = fmaf(c3.w, tv, y3);
                }
            }
        }
        *(float4*)(g_y + ((size_t)b * 128 + c) * 4) = make_float4(y0, y1, y2, y3);
    }
}

// ---------------- irrep-wise linear + flatten ----------------
__global__ void k_lin(const float* __restrict__ wl, float* __restrict__ out) {
    __shared__ float sY[8 * 512]; // 16KB
    const int tid = threadIdx.x;
    const int b0 = blockIdx.x * 8;
#pragma unroll
    for (int it = 0; it < 8; it++)
        ((float4*)sY)[tid + it * 128] = ((const float4*)(g_y + (size_t)b0 * 512))[tid + it * 128];
    __syncthreads();

    const int n = tid;
    float acc[8][4];
#pragma unroll
    for (int bb = 0; bb < 8; bb++)
#pragma unroll
        for (int o = 0; o < 4; o++) acc[bb][o] = 0.f;

    for (int cc = 0; cc < 128; cc++) {
        float w0  = wl[cc * 128 + n];
        float w1v = wl[16384 + cc * 128 + n];
#pragma unroll
        for (int bb = 0; bb < 8; bb++) {
            float4 yv = *(const float4*)(sY + bb * 512 + cc * 4);
            acc[bb][0] = fmaf(yv.x, w0,  acc[bb][0]);
            acc[bb][1] = fmaf(yv.y, w1v, acc[bb][1]);
            acc[bb][2] = fmaf(yv.z, w1v, acc[bb][2]);
            acc[bb][3] = fmaf(yv.w, w1v, acc[bb][3]);
        }
    }
    const float scale = 0.08838834764831843f; // 1/sqrt(128)
#pragma unroll
    for (int bb = 0; bb < 8; bb++) {
        float* op = out + (size_t)(b0 + bb) * 512;
        op[n]               = acc[bb][0] * scale;
        op[128 + n * 3 + 0] = acc[bb][1] * scale;
        op[128 + n * 3 + 1] = acc[bb][2] * scale;
        op[128 + n * 3 + 2] = acc[bb][3] * scale;
    }
}

// ---------------- launch ----------------
extern "C" void kernel_launch(void* const* d_in, const int* in_sizes, int n_in,
                              void* d_out, int out_size) {
    const float* node_feats = (const float*)d_in[0];
    const float* u3_0 = (const float*)d_in[1];
    const float* u3_1 = (const float*)d_in[2];
    const float* u2_0 = (const float*)d_in[3];
    const float* u2_1 = (const float*)d_in[4];
    const float* u1_0 = (const float*)d_in[5];
    const float* u1_1 = (const float*)d_in[6];
    const float* w3   = (const float*)d_in[7];
    const float* w2   = (const float*)d_in[8];
    const float* w1   = (const float*)d_in[9];
    const float* wlin = (const float*)d_in[10];
    const int*   spec = (const int*)d_in[11];
    float* out = (float*)d_out;

    k_presym<<<NM3 + 1, 96>>>(u3_0, u3_1, u2_0, u2_1);
    k_sort<<<1, 1024>>>(spec);
    k_fold<<<dim3(52, 4), 256>>>(w3, w2, w1, u1_0, u1_1);
    k_main_sym<<<dim3(128, 4, 2), TMS>>>(node_feats);
    k_lin<<<128, 128>>>(wlin, out);
}

// round 7
// speedup vs baseline: 1.1738x; 1.1738x over previous
#include <cuda_runtime.h>

#define BN 1024
#define CN 128
#define DN 16
#define SN 4
#define K3C 23
#define K2C 5
#define K1C 2

#define NM3 816   // C(18,3) sorted triples i>=j>=l
#define NM2 136   // C(17,2) sorted pairs  i>=j
// duplicated stream: every coefficient stored twice ({c,c} for f32x2 lanes)
// layout (floats): [c3: 816*8][c2: 136*8][c1: 16*8] = 7744 floats per (e,c)
#define STREAM2 7744

// ---------------- scratch ----------------
__device__ float g_us3[NM3 * 4 * K3C];                 // [m3][oc][k]
__device__ float g_us2[NM2 * 4 * K2C];                 // [m2][oc][k]
__device__ float g_stream[(size_t)SN * CN * STREAM2];  // [e][c][7744]
__device__ int   g_sorted[BN];
__device__ int   g_off[SN + 1];
__device__ float g_y[(size_t)BN * CN * 4];             // [b][c][oc]

// ---------------- f32x2 packed helpers ----------------
__device__ __forceinline__ unsigned long long f2_pack(float lo, float hi) {
    unsigned long long d;
    asm("mov.b64 %0, {%1, %2};" : "=l"(d) : "f"(lo), "f"(hi));
    return d;
}
__device__ __forceinline__ void f2_unpack(float& lo, float& hi, unsigned long long v) {
    asm("mov.b64 {%0, %1}, %2;" : "=f"(lo), "=f"(hi) : "l"(v));
}
__device__ __forceinline__ unsigned long long f2_fma(unsigned long long a, unsigned long long b,
                                                     unsigned long long c) {
    unsigned long long d;
    asm("fma.rn.f32x2 %0, %1, %2, %3;" : "=l"(d) : "l"(a), "l"(b), "l"(c));
    return d;
}
__device__ __forceinline__ unsigned long long f2_mul(unsigned long long a, unsigned long long b) {
    unsigned long long d;
    asm("mul.rn.f32x2 %0, %1, %2;" : "=l"(d) : "l"(a), "l"(b));
    return d;
}

// ---------------- prep: presym3 (blocks 0..815), presym2 (816), sort (817) ----------------
__global__ void k_prep(const float* __restrict__ u3_0, const float* __restrict__ u3_1,
                       const float* __restrict__ u2_0, const float* __restrict__ u2_1,
                       const int* __restrict__ species) {
    const int m = blockIdx.x;
    const int tid = threadIdx.x; // 128
    if (m < NM3) {
        if (tid >= 4 * K3C) return;
        const int oc = tid / K3C, k = tid - oc * K3C;
        int i = 0;
        while ((i + 1) * (i + 2) * (i + 3) / 6 <= m) i++;
        int r = m - i * (i + 1) * (i + 2) / 6;
        int j = 0;
        while ((j + 1) * (j + 2) / 2 <= r) j++;
        int l = r - j * (j + 1) / 2;

        auto val = [&](int a, int b, int d) -> float {
            return (oc == 0) ? u3_0[((a * 16 + b) * 16 + d) * K3C + k]
                             : u3_1[((((oc - 1) * 16 + a) * 16 + b) * 16 + d) * K3C + k];
        };
        float s;
        if (i == j && j == l)      s = val(i, i, i);
        else if (i == j)           s = val(i, i, l) + val(i, l, i) + val(l, i, i);
        else if (j == l)           s = val(i, j, j) + val(j, i, j) + val(j, j, i);
        else                       s = val(i, j, l) + val(i, l, j) + val(j, i, l)
                                     + val(j, l, i) + val(l, i, j) + val(l, j, i);
        g_us3[(m * 4 + oc) * K3C + k] = s;
    } else if (m == NM3) {
        for (int idx = tid; idx < NM2 * 4 * K2C; idx += 128) {
            int m2 = idx / (4 * K2C);
            int rem = idx - m2 * (4 * K2C);
            int oc = rem / K2C, k = rem - oc * K2C;
            int i = 0;
            while ((i + 1) * (i + 2) / 2 <= m2) i++;
            int j = m2 - i * (i + 1) / 2;
            float s = (oc == 0) ? u2_0[(i * 16 + j) * K2C + k]
                                : u2_1[(((oc - 1) * 16 + i) * 16 + j) * K2C + k];
            if (i != j)
                s += (oc == 0) ? u2_0[(j * 16 + i) * K2C + k]
                               : u2_1[(((oc - 1) * 16 + j) * 16 + i) * K2C + k];
            g_us2[idx] = s;
        }
    } else {
        // counting sort by species (order within species irrelevant)
        __shared__ int cnt[SN], cur[SN], off[SN + 1];
        if (tid < SN) { cnt[tid] = 0; cur[tid] = 0; }
        __syncthreads();
        for (int idx = tid; idx < BN; idx += 128) atomicAdd(&cnt[species[idx]], 1);
        __syncthreads();
        if (tid == 0) {
            off[0] = 0;
            for (int e = 0; e < SN; e++) off[e + 1] = off[e] + cnt[e];
            for (int e = 0; e <= SN; e++) g_off[e] = off[e];
        }
        __syncthreads();
        for (int idx = tid; idx < BN; idx += 128) {
            int s = species[idx];
            int pos = off[s] + atomicAdd(&cur[s], 1);
            g_sorted[pos] = idx;
        }
    }
}

// ---------------- fold: build DUPLICATED coefficient streams ----------------
// grid (52, 4): x<51 -> corr3 tile of 16 monomials; x==51 -> corr2 + corr1.
__global__ void k_fold(const float* __restrict__ w3, const float* __restrict__ w2,
                       const float* __restrict__ w1,
                       const float* __restrict__ u1_0, const float* __restrict__ u1_1) {
    __shared__ float sA[2 * K3C * 128]; // 5888
    __shared__ float sB[NM2 * 4 * K2C]; // 2720
    const int tid = threadIdx.x;        // 256
    const int e = blockIdx.y;
    const int c = tid & 127, h = tid >> 7;
    float* outp = g_stream + ((size_t)(e * 128 + c)) * STREAM2;

    if (blockIdx.x < 51) {
        const int mt = blockIdx.x * 16;
        for (int idx = tid; idx < 2 * K3C * 128; idx += 256) {
            int br = idx / (K3C * 128);
            int rem = idx - br * (K3C * 128);
            int k = rem >> 7, cc = rem & 127;
            sA[idx] = w3[(((size_t)(br * 4 + e) * K3C + k) * 128) + cc];
        }
        for (int idx = tid; idx < 16 * 4 * K3C; idx += 256)
            sB[idx] = g_us3[mt * 4 * K3C + idx];
        __syncthreads();

        for (int mm = h; mm < 16; mm += 2) {
            const float* u0 = sB + (mm * 4 + 0) * K3C;
            const float* u1p = sB + (mm * 4 + 1) * K3C;
            const float* u2p = sB + (mm * 4 + 2) * K3C;
            const float* u3p = sB + (mm * 4 + 3) * K3C;
            float a0 = 0.f, a1 = 0.f, a2 = 0.f, a3 = 0.f;
#pragma unroll
            for (int k = 0; k < K3C; k++) {
                float w0  = sA[k * 128 + c];
                float w1v = sA[K3C * 128 + k * 128 + c];
                a0 = fmaf(u0[k],  w0,  a0);
                a1 = fmaf(u1p[k], w1v, a1);
                a2 = fmaf(u2p[k], w1v, a2);
                a3 = fmaf(u3p[k], w1v, a3);
            }
            *(float4*)(outp + (size_t)(mt + mm) * 8)     = make_float4(a0, a0, a1, a1);
            *(float4*)(outp + (size_t)(mt + mm) * 8 + 4) = make_float4(a2, a2, a3, a3);
        }
    } else {
        for (int idx = tid; idx < 2 * K2C * 128; idx += 256) {
            int br = idx / (K2C * 128);
            int rem = idx - br * (K2C * 128);
            int k = rem >> 7, cc = rem & 127;
            sA[idx] = w2[(((size_t)(br * 4 + e) * K2C + k) * 128) + cc];
        }
        for (int idx = tid; idx < 2 * K1C * 128; idx += 256) {
            int br = idx / (K1C * 128);
            int rem = idx - br * (K1C * 128);
            int k = rem >> 7, cc = rem & 127;
            sA[1280 + idx] = w1[(((size_t)(br * 4 + e) * K1C + k) * 128) + cc];
        }
        for (int idx = tid; idx < 4 * 16 * K1C; idx += 256) {
            int oc = idx / (16 * K1C);
            int rem = idx - oc * (16 * K1C);
            int i = rem / K1C, k = rem % K1C;
            sA[1792 + idx] = (oc == 0) ? u1_0[i * K1C + k]
                                       : u1_1[((oc - 1) * 16 + i) * K1C + k];
        }
        for (int idx = tid; idx < NM2 * 4 * K2C; idx += 256)
            sB[idx] = g_us2[idx];
        __syncthreads();

        for (int m = h; m < NM2; m += 2) {
            float a0 = 0.f, a1 = 0.f, a2 = 0.f, a3 = 0.f;
#pragma unroll
            for (int k = 0; k < K2C; k++) {
                float w0  = sA[k * 128 + c];
                float w1v = sA[K2C * 128 + k * 128 + c];
                a0 = fmaf(sB[(m * 4 + 0) * K2C + k], w0,  a0);
                a1 = fmaf(sB[(m * 4 + 1) * K2C + k], w1v, a1);
                a2 = fmaf(sB[(m * 4 + 2) * K2C + k], w1v, a2);
                a3 = fmaf(sB[(m * 4 + 3) * K2C + k], w1v, a3);
            }
            *(float4*)(outp + NM3 * 8 + (size_t)m * 8)     = make_float4(a0, a0, a1, a1);
            *(float4*)(outp + NM3 * 8 + (size_t)m * 8 + 4) = make_float4(a2, a2, a3, a3);
        }
        for (int i = h; i < 16; i += 2) {
            float a0 = 0.f, a1 = 0.f, a2 = 0.f, a3 = 0.f;
#pragma unroll
            for (int k = 0; k < K1C; k++) {
                float w0  = sA[1280 + k * 128 + c];
                float w1v = sA[1280 + K1C * 128 + k * 128 + c];
                a0 = fmaf(sA[1792 + (0 * 16 + i) * K1C + k], w0,  a0);
                a1 = fmaf(sA[1792 + (1 * 16 + i) * K1C + k], w1v, a1);
                a2 = fmaf(sA[1792 + (2 * 16 + i) * K1C + k], w1v, a2);
                a3 = fmaf(sA[1792 + (3 * 16 + i) * K1C + k], w1v, a3);
            }
            *(float4*)(outp + (NM3 + NM2) * 8 + (size_t)i * 8)     = make_float4(a0, a0, a1, a1);
            *(float4*)(outp + (NM3 + NM2) * 8 + (size_t)i * 8 + 4) = make_float4(a2, a2, a3, a3);
        }
    }
}

// ---------------- main: packed f32x2 symmetric monomial evaluation ----------------
// grid (c=128, e=4), 128 threads, 2 nodes/thread packed into f32x2 lanes
#define TMS 128
__global__ __launch_bounds__(TMS, 4) void k_main_sym(const float* __restrict__ xg) {
    __shared__ __align__(16) unsigned long long sC[STREAM2 / 2]; // 3872 u64 = 31KB
    const int c = blockIdx.x, e = blockIdx.y;
    const int tid = threadIdx.x;

    {
        const float4* gs = (const float4*)(g_stream + ((size_t)(e * 128 + c)) * STREAM2);
        float4* s4 = (float4*)sC;
        for (int idx = tid; idx < STREAM2 / 4; idx += TMS) s4[idx] = gs[idx];
    }
    const int lo = g_off[e], hi = g_off[e + 1];
    __syncthreads();

    const ulonglong2* pc = (const ulonglong2*)sC;
    // c3 entries: [2*m3], [2*m3+1]; c2 base 1632; c1 base 1904 (ulonglong2 units)

    for (int t0 = lo + tid; t0 < hi; t0 += 2 * TMS) {
        const int t1 = t0 + TMS;
        const bool v1 = (t1 < hi);
        const int b0 = g_sorted[t0];
        const int b1 = v1 ? g_sorted[t1] : b0;

        unsigned long long xp[16];
        {
            const float4* q0 = (const float4*)(xg + ((size_t)b0 * 128 + c) * 16);
            const float4* q1 = (const float4*)(xg + ((size_t)b1 * 128 + c) * 16);
#pragma unroll
            for (int q = 0; q < 4; q++) {
                float4 a = q0[q];
                float4 b = q1[q];
                xp[4 * q + 0] = f2_pack(a.x, b.x);
                xp[4 * q + 1] = f2_pack(a.y, b.y);
                xp[4 * q + 2] = f2_pack(a.z, b.z);
                xp[4 * q + 3] = f2_pack(a.w, b.w);
            }
        }

        unsigned long long y0 = 0ull, y1 = 0ull, y2 = 0ull, y3 = 0ull;
        int m3 = 0, m2 = 0;
#pragma unroll
        for (int i = 0; i < 16; i++) {
            {
                const ulonglong2 A = pc[1904 + 2 * i];
                const ulonglong2 B = pc[1904 + 2 * i + 1];
                y0 = f2_fma(A.x, xp[i], y0);
                y1 = f2_fma(A.y, xp[i], y1);
                y2 = f2_fma(B.x, xp[i], y2);
                y3 = f2_fma(B.y, xp[i], y3);
            }
#pragma unroll
            for (int j = 0; j <= i; j++) {
                const unsigned long long q = f2_mul(xp[i], xp[j]);
                const ulonglong2 C2a = pc[1632 + 2 * m2];
                const ulonglong2 C2b = pc[1632 + 2 * m2 + 1];
                m2++;
                unsigned long long s0 = C2a.x, s1 = C2a.y, s2 = C2b.x, s3 = C2b.y;
#pragma unroll
                for (int l = 0; l <= j; l++) {
                    const ulonglong2 A3 = pc[2 * m3];
                    const ulonglong2 B3 = pc[2 * m3 + 1];
                    m3++;
                    s0 = f2_fma(A3.x, xp[l], s0);
                    s1 = f2_fma(A3.y, xp[l], s1);
                    s2 = f2_fma(B3.x, xp[l], s2);
                    s3 = f2_fma(B3.y, xp[l], s3);
                }
                y0 = f2_fma(s0, q, y0);
                y1 = f2_fma(s1, q, y1);
                y2 = f2_fma(s2, q, y2);
                y3 = f2_fma(s3, q, y3);
            }
        }
        float a0, b0v, a1, b1v, a2, b2v, a3, b3v;
        f2_unpack(a0, b0v, y0);
        f2_unpack(a1, b1v, y1);
        f2_unpack(a2, b2v, y2);
        f2_unpack(a3, b3v, y3);
        *(float4*)(g_y + ((size_t)b0 * 128 + c) * 4) = make_float4(a0, a1, a2, a3);
        if (v1)
            *(float4*)(g_y + ((size_t)b1 * 128 + c) * 4) = make_float4(b0v, b1v, b2v, b3v);
    }
}

// ---------------- irrep-wise linear + flatten ----------------
// grid 256 blocks, 128 threads, 4 nodes per block
__global__ void k_lin(const float* __restrict__ wl, float* __restrict__ out) {
    __shared__ float sY[4 * 512]; // 8KB
    const int tid = threadIdx.x;
    const int b0 = blockIdx.x * 4;
#pragma unroll
    for (int it = 0; it < 4; it++)
        ((float4*)sY)[tid + it * 128] = ((const float4*)(g_y + (size_t)b0 * 512))[tid + it * 128];
    __syncthreads();

    const int n = tid;
    float acc[4][4];
#pragma unroll
    for (int bb = 0; bb < 4; bb++)
#pragma unroll
        for (int o = 0; o < 4; o++) acc[bb][o] = 0.f;

    for (int cc = 0; cc < 128; cc++) {
        float w0  = wl[cc * 128 + n];
        float w1v = wl[16384 + cc * 128 + n];
#pragma unroll
        for (int bb = 0; bb < 4; bb++) {
            float4 yv = *(const float4*)(sY + bb * 512 + cc * 4);
            acc[bb][0] = fmaf(yv.x, w0,  acc[bb][0]);
            acc[bb][1] = fmaf(yv.y, w1v, acc[bb][1]);
            acc[bb][2] = fmaf(yv.z, w1v, acc[bb][2]);
            acc[bb][3] = fmaf(yv.w, w1v, acc[bb][3]);
        }
    }
    const float scale = 0.08838834764831843f; // 1/sqrt(128)
#pragma unroll
    for (int bb = 0; bb < 4; bb++) {
        float* op = out + (size_t)(b0 + bb) * 512;
        op[n]               = acc[bb][0] * scale;
        op[128 + n * 3 + 0] = acc[bb][1] * scale;
        op[128 + n * 3 + 1] = acc[bb][2] * scale;
        op[128 + n * 3 + 2] = acc[bb][3] * scale;
    }
}

// ---------------- launch ----------------
extern "C" void kernel_launch(void* const* d_in, const int* in_sizes, int n_in,
                              void* d_out, int out_size) {
    const float* node_feats = (const float*)d_in[0];
    const float* u3_0 = (const float*)d_in[1];
    const float* u3_1 = (const float*)d_in[2];
    const float* u2_0 = (const float*)d_in[3];
    const float* u2_1 = (const float*)d_in[4];
    const float* u1_0 = (const float*)d_in[5];
    const float* u1_1 = (const float*)d_in[6];
    const float* w3   = (const float*)d_in[7];
    const float* w2   = (const float*)d_in[8];
    const float* w1   = (const float*)d_in[9];
    const float* wlin = (const float*)d_in[10];
    const int*   spec = (const int*)d_in[11];
    float* out = (float*)d_out;

    k_prep<<<NM3 + 2, 128>>>(u3_0, u3_1, u2_0, u2_1, spec);
    k_fold<<<dim3(52, 4), 256>>>(w3, w2, w1, u1_0, u1_1);
    k_main_sym<<<dim3(128, 4), TMS>>>(node_feats);
    k_lin<<<256, 128>>>(wlin, out);
}

// round 9
// speedup vs baseline: 1.1907x; 1.0144x over previous
#include <cuda_runtime.h>

#define BN 1024
#define CN 128
#define DN 16
#define SN 4
#define K3C 23
#define K2C 5
#define K1C 2

#define NM3 816   // C(18,3) sorted triples i>=j>=l
#define NM2 136   // C(17,2) sorted pairs  i>=j
// duplicated stream: every coefficient stored twice ({c,c} for f32x2 lanes)
// layout (floats): [c3: 816*8][c2: 136*8][c1: 16*8] = 7744 floats per (e,c)
#define STREAM2 7744

// ---------------- scratch ----------------
__device__ float g_us3[NM3 * 4 * K3C];                 // [m3][oc][k]
__device__ float g_us2[NM2 * 4 * K2C];                 // [m2][oc][k]
__device__ float g_stream[(size_t)SN * CN * STREAM2];  // [e][c][7744]
__device__ int   g_sorted[BN];
__device__ int   g_off[SN + 1];
__device__ float g_y[(size_t)BN * CN * 4];             // [b][c][oc]

// ---------------- f32x2 packed helpers ----------------
__device__ __forceinline__ unsigned long long f2_pack(float lo, float hi) {
    unsigned long long d;
    asm("mov.b64 %0, {%1, %2};" : "=l"(d) : "f"(lo), "f"(hi));
    return d;
}
__device__ __forceinline__ void f2_unpack(float& lo, float& hi, unsigned long long v) {
    asm("mov.b64 {%0, %1}, %2;" : "=f"(lo), "=f"(hi) : "l"(v));
}
__device__ __forceinline__ unsigned long long f2_fma(unsigned long long a, unsigned long long b,
                                                     unsigned long long c) {
    unsigned long long d;
    asm("fma.rn.f32x2 %0, %1, %2, %3;" : "=l"(d) : "l"(a), "l"(b), "l"(c));
    return d;
}
__device__ __forceinline__ unsigned long long f2_mul(unsigned long long a, unsigned long long b) {
    unsigned long long d;
    asm("mul.rn.f32x2 %0, %1, %2;" : "=l"(d) : "l"(a), "l"(b));
    return d;
}

// ---------------- prep: presym3 (blocks 0..815), presym2 (816), sort (817) ----------------
__global__ void k_prep(const float* __restrict__ u3_0, const float* __restrict__ u3_1,
                       const float* __restrict__ u2_0, const float* __restrict__ u2_1,
                       const int* __restrict__ species) {
    const int m = blockIdx.x;
    const int tid = threadIdx.x; // 128
    if (m < NM3) {
        if (tid >= 4 * K3C) return;
        const int oc = tid / K3C, k = tid - oc * K3C;
        int i = 0;
        while ((i + 1) * (i + 2) * (i + 3) / 6 <= m) i++;
        int r = m - i * (i + 1) * (i + 2) / 6;
        int j = 0;
        while ((j + 1) * (j + 2) / 2 <= r) j++;
        int l = r - j * (j + 1) / 2;

        auto val = [&](int a, int b, int d) -> float {
            return (oc == 0) ? u3_0[((a * 16 + b) * 16 + d) * K3C + k]
                             : u3_1[((((oc - 1) * 16 + a) * 16 + b) * 16 + d) * K3C + k];
        };
        float s;
        if (i == j && j == l)      s = val(i, i, i);
        else if (i == j)           s = val(i, i, l) + val(i, l, i) + val(l, i, i);
        else if (j == l)           s = val(i, j, j) + val(j, i, j) + val(j, j, i);
        else                       s = val(i, j, l) + val(i, l, j) + val(j, i, l)
                                     + val(j, l, i) + val(l, i, j) + val(l, j, i);
        g_us3[(m * 4 + oc) * K3C + k] = s;
    } else if (m == NM3) {
        for (int idx = tid; idx < NM2 * 4 * K2C; idx += 128) {
            int m2 = idx / (4 * K2C);
            int rem = idx - m2 * (4 * K2C);
            int oc = rem / K2C, k = rem - oc * K2C;
            int i = 0;
            while ((i + 1) * (i + 2) / 2 <= m2) i++;
            int j = m2 - i * (i + 1) / 2;
            float s = (oc == 0) ? u2_0[(i * 16 + j) * K2C + k]
                                : u2_1[(((oc - 1) * 16 + i) * 16 + j) * K2C + k];
            if (i != j)
                s += (oc == 0) ? u2_0[(j * 16 + i) * K2C + k]
                               : u2_1[(((oc - 1) * 16 + j) * 16 + i) * K2C + k];
            g_us2[idx] = s;
        }
    } else {
        // counting sort by species (order within species irrelevant)
        __shared__ int cnt[SN], cur[SN], off[SN + 1];
        if (tid < SN) { cnt[tid] = 0; cur[tid] = 0; }
        __syncthreads();
        for (int idx = tid; idx < BN; idx += 128) atomicAdd(&cnt[species[idx]], 1);
        __syncthreads();
        if (tid == 0) {
            off[0] = 0;
            for (int e = 0; e < SN; e++) off[e + 1] = off[e] + cnt[e];
            for (int e = 0; e <= SN; e++) g_off[e] = off[e];
        }
        __syncthreads();
        for (int idx = tid; idx < BN; idx += 128) {
            int s = species[idx];
            int pos = off[s] + atomicAdd(&cur[s], 1);
            g_sorted[pos] = idx;
        }
    }
}

// ---------------- fold: build DUPLICATED coefficient streams ----------------
// grid (52, 4): x<51 -> corr3 tile of 16 monomials; x==51 -> corr2 + corr1.
__global__ void k_fold(const float* __restrict__ w3, const float* __restrict__ w2,
                       const float* __restrict__ w1,
                       const float* __restrict__ u1_0, const float* __restrict__ u1_1) {
    __shared__ float sA[2 * K3C * 128]; // 5888
    __shared__ float sB[NM2 * 4 * K2C]; // 2720
    const int tid = threadIdx.x;        // 256
    const int e = blockIdx.y;
    const int c = tid & 127, h = tid >> 7;
    float* outp = g_stream + ((size_t)(e * 128 + c)) * STREAM2;

    if (blockIdx.x < 51) {
        const int mt = blockIdx.x * 16;
        for (int idx = tid; idx < 2 * K3C * 128; idx += 256) {
            int br = idx / (K3C * 128);
            int rem = idx - br * (K3C * 128);
            int k = rem >> 7, cc = rem & 127;
            sA[idx] = w3[(((size_t)(br * 4 + e) * K3C + k) * 128) + cc];
        }
        for (int idx = tid; idx < 16 * 4 * K3C; idx += 256)
            sB[idx] = g_us3[mt * 4 * K3C + idx];
        __syncthreads();

        for (int mm = h; mm < 16; mm += 2) {
            const float* u0 = sB + (mm * 4 + 0) * K3C;
            const float* u1p = sB + (mm * 4 + 1) * K3C;
            const float* u2p = sB + (mm * 4 + 2) * K3C;
            const float* u3p = sB + (mm * 4 + 3) * K3C;
            float a0 = 0.f, a1 = 0.f, a2 = 0.f, a3 = 0.f;
#pragma unroll
            for (int k = 0; k < K3C; k++) {
                float w0  = sA[k * 128 + c];
                float w1v = sA[K3C * 128 + k * 128 + c];
                a0 = fmaf(u0[k],  w0,  a0);
                a1 = fmaf(u1p[k], w1v, a1);
                a2 = fmaf(u2p[k], w1v, a2);
                a3 = fmaf(u3p[k], w1v, a3);
            }
            *(float4*)(outp + (size_t)(mt + mm) * 8)     = make_float4(a0, a0, a1, a1);
            *(float4*)(outp + (size_t)(mt + mm) * 8 + 4) = make_float4(a2, a2, a3, a3);
        }
    } else {
        for (int idx = tid; idx < 2 * K2C * 128; idx += 256) {
            int br = idx / (K2C * 128);
            int rem = idx - br * (K2C * 128);
            int k = rem >> 7, cc = rem & 127;
            sA[idx] = w2[(((size_t)(br * 4 + e) * K2C + k) * 128) + cc];
        }
        for (int idx = tid; idx < 2 * K1C * 128; idx += 256) {
            int br = idx / (K1C * 128);
            int rem = idx - br * (K1C * 128);
            int k = rem >> 7, cc = rem & 127;
            sA[1280 + idx] = w1[(((size_t)(br * 4 + e) * K1C + k) * 128) + cc];
        }
        for (int idx = tid; idx < 4 * 16 * K1C; idx += 256) {
            int oc = idx / (16 * K1C);
            int rem = idx - oc * (16 * K1C);
            int i = rem / K1C, k = rem % K1C;
            sA[1792 + idx] = (oc == 0) ? u1_0[i * K1C + k]
                                       : u1_1[((oc - 1) * 16 + i) * K1C + k];
        }
        for (int idx = tid; idx < NM2 * 4 * K2C; idx += 256)
            sB[idx] = g_us2[idx];
        __syncthreads();

        for (int m = h; m < NM2; m += 2) {
            float a0 = 0.f, a1 = 0.f, a2 = 0.f, a3 = 0.f;
#pragma unroll
            for (int k = 0; k < K2C; k++) {
                float w0  = sA[k * 128 + c];
                float w1v = sA[K2C * 128 + k * 128 + c];
                a0 = fmaf(sB[(m * 4 + 0) * K2C + k], w0,  a0);
                a1 = fmaf(sB[(m * 4 + 1) * K2C + k], w1v, a1);
                a2 = fmaf(sB[(m * 4 + 2) * K2C + k], w1v, a2);
                a3 = fmaf(sB[(m * 4 + 3) * K2C + k], w1v, a3);
            }
            *(float4*)(outp + NM3 * 8 + (size_t)m * 8)     = make_float4(a0, a0, a1, a1);
            *(float4*)(outp + NM3 * 8 + (size_t)m * 8 + 4) = make_float4(a2, a2, a3, a3);
        }
        for (int i = h; i < 16; i += 2) {
            float a0 = 0.f, a1 = 0.f, a2 = 0.f, a3 = 0.f;
#pragma unroll
            for (int k = 0; k < K1C; k++) {
                float w0  = sA[1280 + k * 128 + c];
                float w1v = sA[1280 + K1C * 128 + k * 128 + c];
                a0 = fmaf(sA[1792 + (0 * 16 + i) * K1C + k], w0,  a0);
                a1 = fmaf(sA[1792 + (1 * 16 + i) * K1C + k], w1v, a1);
                a2 = fmaf(sA[1792 + (2 * 16 + i) * K1C + k], w1v, a2);
                a3 = fmaf(sA[1792 + (3 * 16 + i) * K1C + k], w1v, a3);
            }
            *(float4*)(outp + (NM3 + NM2) * 8 + (size_t)i * 8)     = make_float4(a0, a0, a1, a1);
            *(float4*)(outp + (NM3 + NM2) * 8 + (size_t)i * 8 + 4) = make_float4(a2, a2, a3, a3);
        }
    }
}

// ---------------- main: packed f32x2 symmetric monomial evaluation ----------------
// grid (c=128, e=4), 128 threads, 2 nodes/thread packed into f32x2 lanes
#define TMS 128
__global__ __launch_bounds__(TMS, 4) void k_main_sym(const float* __restrict__ xg) {
    __shared__ __align__(16) unsigned long long sC[STREAM2 / 2]; // 3872 u64 = 31KB
    const int c = blockIdx.x, e = blockIdx.y;
    const int tid = threadIdx.x;

    {
        const float4* gs = (const float4*)(g_stream + ((size_t)(e * 128 + c)) * STREAM2);
        float4* s4 = (float4*)sC;
        for (int idx = tid; idx < STREAM2 / 4; idx += TMS) s4[idx] = gs[idx];
    }
    const int lo = g_off[e], hi = g_off[e + 1];
    __syncthreads();

    const ulonglong2* pc = (const ulonglong2*)sC;
    // c3 entries: [2*m3], [2*m3+1]; c2 base 1632; c1 base 1904 (ulonglong2 units)

    for (int t0 = lo + tid; t0 < hi; t0 += 2 * TMS) {
        const int t1 = t0 + TMS;
        const bool v1 = (t1 < hi);
        const int b0 = g_sorted[t0];
        const int b1 = v1 ? g_sorted[t1] : b0;

        unsigned long long xp[16];
        {
            const float4* q0 = (const float4*)(xg + ((size_t)b0 * 128 + c) * 16);
            const float4* q1 = (const float4*)(xg + ((size_t)b1 * 128 + c) * 16);
#pragma unroll
            for (int q = 0; q < 4; q++) {
                float4 a = q0[q];
                float4 b = q1[q];
                xp[4 * q + 0] = f2_pack(a.x, b.x);
                xp[4 * q + 1] = f2_pack(a.y, b.y);
                xp[4 * q + 2] = f2_pack(a.z, b.z);
                xp[4 * q + 3] = f2_pack(a.w, b.w);
            }
        }

        unsigned long long y0 = 0ull, y1 = 0ull, y2 = 0ull, y3 = 0ull;
        int m3 = 0, m2 = 0;
#pragma unroll
        for (int i = 0; i < 16; i++) {
            {
                const ulonglong2 A = pc[1904 + 2 * i];
                const ulonglong2 B = pc[1904 + 2 * i + 1];
                y0 = f2_fma(A.x, xp[i], y0);
                y1 = f2_fma(A.y, xp[i], y1);
                y2 = f2_fma(B.x, xp[i], y2);
                y3 = f2_fma(B.y, xp[i], y3);
            }
#pragma unroll
            for (int j = 0; j <= i; j++) {
                const unsigned long long q = f2_mul(xp[i], xp[j]);
                const ulonglong2 C2a = pc[1632 + 2 * m2];
                const ulonglong2 C2b = pc[1632 + 2 * m2 + 1];
                m2++;
                unsigned long long s0 = C2a.x, s1 = C2a.y, s2 = C2b.x, s3 = C2b.y;
#pragma unroll
                for (int l = 0; l <= j; l++) {
                    const ulonglong2 A3 = pc[2 * m3];
                    const ulonglong2 B3 = pc[2 * m3 + 1];
                    m3++;
                    s0 = f2_fma(A3.x, xp[l], s0);
                    s1 = f2_fma(A3.y, xp[l], s1);
                    s2 = f2_fma(B3.x, xp[l], s2);
                    s3 = f2_fma(B3.y, xp[l], s3);
                }
                y0 = f2_fma(s0, q, y0);
                y1 = f2_fma(s1, q, y1);
                y2 = f2_fma(s2, q, y2);
                y3 = f2_fma(s3, q, y3);
            }
        }
        float a0, b0v, a1, b1v, a2, b2v, a3, b3v;
        f2_unpack(a0, b0v, y0);
        f2_unpack(a1, b1v, y1);
        f2_unpack(a2, b2v, y2);
        f2_unpack(a3, b3v, y3);
        *(float4*)(g_y + ((size_t)b0 * 128 + c) * 4) = make_float4(a0, a1, a2, a3);
        if (v1)
            *(float4*)(g_y + ((size_t)b1 * 128 + c) * 4) = make_float4(b0v, b1v, b2v, b3v);
    }
}

// ---------------- irrep-wise linear + flatten ----------------
// grid 512 blocks, 256 threads: 2 nodes/block, cc-loop split across 2 thread halves
__global__ __launch_bounds__(256) void k_lin(const float* __restrict__ wl, float* __restrict__ out) {
    __shared__ float sY[2 * 512];       // 4KB: 2 nodes of y[b][c][oc]
    __shared__ float sP[2 * 4 * 128];   // 4KB: partial sums from half h=1
    const int tid = threadIdx.x;
    const int b0 = blockIdx.x * 2;
    const int n = tid & 127, h = tid >> 7;

    ((float4*)sY)[tid] = ((const float4*)(g_y + (size_t)b0 * 512))[tid];
    __syncthreads();

    float acc[2][4];
#pragma unroll
    for (int bb = 0; bb < 2; bb++)
#pragma unroll
        for (int o = 0; o < 4; o++) acc[bb][o] = 0.f;

    const int c0 = h * 64;
#pragma unroll 4
    for (int cc = c0; cc < c0 + 64; cc++) {
        float w0  = wl[cc * 128 + n];
        float w1v = wl[16384 + cc * 128 + n];
#pragma unroll
        for (int bb = 0; bb < 2; bb++) {
            float4 yv = *(const float4*)(sY + bb * 512 + cc * 4);
            acc[bb][0] = fmaf(yv.x, w0,  acc[bb][0]);
            acc[bb][1] = fmaf(yv.y, w1v, acc[bb][1]);
            acc[bb][2] = fmaf(yv.z, w1v, acc[bb][2]);
            acc[bb][3] = fmaf(yv.w, w1v, acc[bb][3]);
        }
    }

    if (h == 1) {
#pragma unroll
        for (int bb = 0; bb < 2; bb++)
#pragma unroll
            for (int o = 0; o < 4; o++) sP[(bb * 4 + o) * 128 + n] = acc[bb][o];
    }
    __syncthreads();
    if (h == 0) {
        const float scale = 0.08838834764831843f; // 1/sqrt(128)
#pragma unroll
        for (int bb = 0; bb < 2; bb++) {
            float* op = out + (size_t)(b0 + bb) * 512;
            float v0 = (acc[bb][0] + sP[(bb * 4 + 0) * 128 + n]) * scale;
            float v1 = (acc[bb][1] + sP[(bb * 4 + 1) * 128 + n]) * scale;
            float v2 = (acc[bb][2] + sP[(bb * 4 + 2) * 128 + n]) * scale;
            float v3 = (acc[bb][3] + sP[(bb * 4 + 3) * 128 + n]) * scale;
            op[n]               = v0;
            op[128 + n * 3 + 0] = v1;
            op[128 + n * 3 + 1] = v2;
            op[128 + n * 3 + 2] = v3;
        }
    }
}

// ---------------- launch ----------------
extern "C" void kernel_launch(void* const* d_in, const int* in_sizes, int n_in,
                              void* d_out, int out_size) {
    const float* node_feats = (const float*)d_in[0];
    const float* u3_0 = (const float*)d_in[1];
    const float* u3_1 = (const float*)d_in[2];
    const float* u2_0 = (const float*)d_in[3];
    const float* u2_1 = (const float*)d_in[4];
    const float* u1_0 = (const float*)d_in[5];
    const float* u1_1 = (const float*)d_in[6];
    const float* w3   = (const float*)d_in[7];
    const float* w2   = (const float*)d_in[8];
    const float* w1   = (const float*)d_in[9];
    const float* wlin = (const float*)d_in[10];
    const int*   spec = (const int*)d_in[11];
    float* out = (float*)d_out;

    k_prep<<<NM3 + 2, 128>>>(u3_0, u3_1, u2_0, u2_1, spec);
    k_fold<<<dim3(52, 4), 256>>>(w3, w2, w1, u1_0, u1_1);
    k_main_sym<<<dim3(128, 4), TMS>>>(node_feats);
    k_lin<<<512, 256>>>(wlin, out);
}

// round 10
// speedup vs baseline: 1.5810x; 1.3278x over previous
#include <cuda_runtime.h>

#define BN 1024
#define CN 128
#define DN 16
#define SN 4
#define K3C 23
#define K2C 5
#define K1C 2

#define NM3 816   // C(18,3) sorted triples i>=j>=l
#define NM2 136   // C(17,2) sorted pairs  i>=j
// compact stream: per monomial one float4 {c_oc0,c_oc1,c_oc2,c_oc3}
// layout (floats): [c3: 816*4][c2: 136*4][c1: 16*4] = 3872 floats per (e,c)
#define STREAM 3872

// ---------------- scratch ----------------
__device__ float g_us3[NM3 * 4 * K3C];                 // [m3][oc][k]
__device__ float g_us2[NM2 * 4 * K2C];                 // [m2][oc][k]
__device__ float g_stream[(size_t)SN * CN * STREAM];   // [e][c][3872]
__device__ float g_wlT[2 * CN * CN];                   // [br][n][cc] transposed w_lin
__device__ int   g_sorted[BN];
__device__ int   g_off[SN + 1];
__device__ float g_y[(size_t)BN * CN * 4];             // [b][c][oc]

// ---------------- f32x2 packed helpers ----------------
__device__ __forceinline__ unsigned long long f2_pack(float lo, float hi) {
    unsigned long long d;
    asm("mov.b64 %0, {%1, %2};" : "=l"(d) : "f"(lo), "f"(hi));
    return d;
}
__device__ __forceinline__ void f2_unpack(float& lo, float& hi, unsigned long long v) {
    asm("mov.b64 {%0, %1}, %2;" : "=f"(lo), "=f"(hi) : "l"(v));
}
__device__ __forceinline__ unsigned long long f2_fma(unsigned long long a, unsigned long long b,
                                                     unsigned long long c) {
    unsigned long long d;
    asm("fma.rn.f32x2 %0, %1, %2, %3;" : "=l"(d) : "l"(a), "l"(b), "l"(c));
    return d;
}
__device__ __forceinline__ unsigned long long f2_mul(unsigned long long a, unsigned long long b) {
    unsigned long long d;
    asm("mul.rn.f32x2 %0, %1, %2;" : "=l"(d) : "l"(a), "l"(b));
    return d;
}

// ---------------- prep: presym3 (0..815), presym2 (816), sort (817), wlT (818..825) ----------------
__global__ void k_prep(const float* __restrict__ u3_0, const float* __restrict__ u3_1,
                       const float* __restrict__ u2_0, const float* __restrict__ u2_1,
                       const int* __restrict__ species, const float* __restrict__ wl) {
    const int m = blockIdx.x;
    const int tid = threadIdx.x; // 128
    if (m < NM3) {
        if (tid >= 4 * K3C) return;
        const int oc = tid / K3C, k = tid - oc * K3C;
        int i = 0;
        while ((i + 1) * (i + 2) * (i + 3) / 6 <= m) i++;
        int r = m - i * (i + 1) * (i + 2) / 6;
        int j = 0;
        while ((j + 1) * (j + 2) / 2 <= r) j++;
        int l = r - j * (j + 1) / 2;

        auto val = [&](int a, int b, int d) -> float {
            return (oc == 0) ? u3_0[((a * 16 + b) * 16 + d) * K3C + k]
                             : u3_1[((((oc - 1) * 16 + a) * 16 + b) * 16 + d) * K3C + k];
        };
        float s;
        if (i == j && j == l)      s = val(i, i, i);
        else if (i == j)           s = val(i, i, l) + val(i, l, i) + val(l, i, i);
        else if (j == l)           s = val(i, j, j) + val(j, i, j) + val(j, j, i);
        else                       s = val(i, j, l) + val(i, l, j) + val(j, i, l)
                                     + val(j, l, i) + val(l, i, j) + val(l, j, i);
        g_us3[(m * 4 + oc) * K3C + k] = s;
    } else if (m == NM3) {
        for (int idx = tid; idx < NM2 * 4 * K2C; idx += 128) {
            int m2 = idx / (4 * K2C);
            int rem = idx - m2 * (4 * K2C);
            int oc = rem / K2C, k = rem - oc * K2C;
            int i = 0;
            while ((i + 1) * (i + 2) / 2 <= m2) i++;
            int j = m2 - i * (i + 1) / 2;
            float s = (oc == 0) ? u2_0[(i * 16 + j) * K2C + k]
                                : u2_1[(((oc - 1) * 16 + i) * 16 + j) * K2C + k];
            if (i != j)
                s += (oc == 0) ? u2_0[(j * 16 + i) * K2C + k]
                               : u2_1[(((oc - 1) * 16 + j) * 16 + i) * K2C + k];
            g_us2[idx] = s;
        }
    } else if (m == NM3 + 1) {
        // counting sort by species (order within species irrelevant)
        __shared__ int cnt[SN], cur[SN], off[SN + 1];
        if (tid < SN) { cnt[tid] = 0; cur[tid] = 0; }
        __syncthreads();
        for (int idx = tid; idx < BN; idx += 128) atomicAdd(&cnt[species[idx]], 1);
        __syncthreads();
        if (tid == 0) {
            off[0] = 0;
            for (int e = 0; e < SN; e++) off[e + 1] = off[e] + cnt[e];
            for (int e = 0; e <= SN; e++) g_off[e] = off[e];
        }
        __syncthreads();
        for (int idx = tid; idx < BN; idx += 128) {
            int s = species[idx];
            int pos = off[s] + atomicAdd(&cur[s], 1);
            g_sorted[pos] = idx;
        }
    } else {
        // transpose w_lin: 8 blocks, each 4096 elements
        int part = m - (NM3 + 2);       // 0..7
        int br = part >> 2, seg = part & 3;
        int base = seg * 4096;
        for (int idx = tid; idx < 4096; idx += 128) {
            int g = base + idx;
            int cc = g >> 7, n = g & 127;
            g_wlT[br * 16384 + n * 128 + cc] = wl[br * 16384 + g];
        }
    }
}

// ---------------- fold: build compact coefficient streams ----------------
// grid (52, 4): x<51 -> corr3 tile of 16 monomials; x==51 -> corr2 + corr1.
__global__ void k_fold(const float* __restrict__ w3, const float* __restrict__ w2,
                       const float* __restrict__ w1,
                       const float* __restrict__ u1_0, const float* __restrict__ u1_1) {
    __shared__ float sA[2 * K3C * 128]; // 5888
    __shared__ float sB[NM2 * 4 * K2C]; // 2720
    const int tid = threadIdx.x;        // 256
    const int e = blockIdx.y;
    const int c = tid & 127, h = tid >> 7;
    float* outp = g_stream + ((size_t)(e * 128 + c)) * STREAM;

    if (blockIdx.x < 51) {
        const int mt = blockIdx.x * 16;
        for (int idx = tid; idx < 2 * K3C * 128; idx += 256) {
            int br = idx / (K3C * 128);
            int rem = idx - br * (K3C * 128);
            int k = rem >> 7, cc = rem & 127;
            sA[idx] = w3[(((size_t)(br * 4 + e) * K3C + k) * 128) + cc];
        }
        for (int idx = tid; idx < 16 * 4 * K3C; idx += 256)
            sB[idx] = g_us3[mt * 4 * K3C + idx];
        __syncthreads();

        for (int mm = h; mm < 16; mm += 2) {
            const float* u0 = sB + (mm * 4 + 0) * K3C;
            const float* u1p = sB + (mm * 4 + 1) * K3C;
            const float* u2p = sB + (mm * 4 + 2) * K3C;
            const float* u3p = sB + (mm * 4 + 3) * K3C;
            float a0 = 0.f, a1 = 0.f, a2 = 0.f, a3 = 0.f;
#pragma unroll
            for (int k = 0; k < K3C; k++) {
                float w0  = sA[k * 128 + c];
                float w1v = sA[K3C * 128 + k * 128 + c];
                a0 = fmaf(u0[k],  w0,  a0);
                a1 = fmaf(u1p[k], w1v, a1);
                a2 = fmaf(u2p[k], w1v, a2);
                a3 = fmaf(u3p[k], w1v, a3);
            }
            *(float4*)(outp + (size_t)(mt + mm) * 4) = make_float4(a0, a1, a2, a3);
        }
    } else {
        for (int idx = tid; idx < 2 * K2C * 128; idx += 256) {
            int br = idx / (K2C * 128);
            int rem = idx - br * (K2C * 128);
            int k = rem >> 7, cc = rem & 127;
            sA[idx] = w2[(((size_t)(br * 4 + e) * K2C + k) * 128) + cc];
        }
        for (int idx = tid; idx < 2 * K1C * 128; idx += 256) {
            int br = idx / (K1C * 128);
            int rem = idx - br * (K1C * 128);
            int k = rem >> 7, cc = rem & 127;
            sA[1280 + idx] = w1[(((size_t)(br * 4 + e) * K1C + k) * 128) + cc];
        }
        for (int idx = tid; idx < 4 * 16 * K1C; idx += 256) {
            int oc = idx / (16 * K1C);
            int rem = idx - oc * (16 * K1C);
            int i = rem / K1C, k = rem % K1C;
            sA[1792 + idx] = (oc == 0) ? u1_0[i * K1C + k]
                                       : u1_1[((oc - 1) * 16 + i) * K1C + k];
        }
        for (int idx = tid; idx < NM2 * 4 * K2C; idx += 256)
            sB[idx] = g_us2[idx];
        __syncthreads();

        for (int m = h; m < NM2; m += 2) {
            float a0 = 0.f, a1 = 0.f, a2 = 0.f, a3 = 0.f;
#pragma unroll
            for (int k = 0; k < K2C; k++) {
                float w0  = sA[k * 128 + c];
                float w1v = sA[K2C * 128 + k * 128 + c];
                a0 = fmaf(sB[(m * 4 + 0) * K2C + k], w0,  a0);
                a1 = fmaf(sB[(m * 4 + 1) * K2C + k], w1v, a1);
                a2 = fmaf(sB[(m * 4 + 2) * K2C + k], w1v, a2);
                a3 = fmaf(sB[(m * 4 + 3) * K2C + k], w1v, a3);
            }
            *(float4*)(outp + NM3 * 4 + (size_t)m * 4) = make_float4(a0, a1, a2, a3);
        }
        for (int i = h; i < 16; i += 2) {
            float a0 = 0.f, a1 = 0.f, a2 = 0.f, a3 = 0.f;
#pragma unroll
            for (int k = 0; k < K1C; k++) {
                float w0  = sA[1280 + k * 128 + c];
                float w1v = sA[1280 + K1C * 128 + k * 128 + c];
                a0 = fmaf(sA[1792 + (0 * 16 + i) * K1C + k], w0,  a0);
                a1 = fmaf(sA[1792 + (1 * 16 + i) * K1C + k], w1v, a1);
                a2 = fmaf(sA[1792 + (2 * 16 + i) * K1C + k], w1v, a2);
                a3 = fmaf(sA[1792 + (3 * 16 + i) * K1C + k], w1v, a3);
            }
            *(float4*)(outp + (NM3 + NM2) * 4 + (size_t)i * 4) = make_float4(a0, a1, a2, a3);
        }
    }
}

// ---------------- main: f32x2 over oc-pairs, 2 nodes/thread ----------------
// grid (c=128, e=4), 128 threads; 1 LDS.128 per monomial serves 4 oc x 2 nodes
#define TMS 128
__global__ __launch_bounds__(TMS, 4) void k_main_sym(const float* __restrict__ xg) {
    __shared__ __align__(16) float sC[STREAM]; // 15.5KB
    const int c = blockIdx.x, e = blockIdx.y;
    const int tid = threadIdx.x;

    {
        const float4* gs = (const float4*)(g_stream + ((size_t)(e * 128 + c)) * STREAM);
        float4* s4 = (float4*)sC;
        for (int idx = tid; idx < STREAM / 4; idx += TMS) s4[idx] = gs[idx];
    }
    const int lo = g_off[e], hi = g_off[e + 1];
    __syncthreads();

    const ulonglong2* pc = (const ulonglong2*)sC;
    // c3 at pc[m3]; c2 at pc[816+m2]; c1 at pc[952+i]
    // pc[i].x = {c_oc0, c_oc1}, pc[i].y = {c_oc2, c_oc3}

    for (int t0 = lo + tid; t0 < hi; t0 += 2 * TMS) {
        const int t1 = t0 + TMS;
        const bool v1 = (t1 < hi);
        const int b0 = g_sorted[t0];
        const int b1 = v1 ? g_sorted[t1] : b0;

        unsigned long long xA[16], xB[16];
        {
            const float4* q0 = (const float4*)(xg + ((size_t)b0 * 128 + c) * 16);
            const float4* q1 = (const float4*)(xg + ((size_t)b1 * 128 + c) * 16);
#pragma unroll
            for (int q = 0; q < 4; q++) {
                float4 a = q0[q];
                xA[4 * q + 0] = f2_pack(a.x, a.x);
                xA[4 * q + 1] = f2_pack(a.y, a.y);
                xA[4 * q + 2] = f2_pack(a.z, a.z);
                xA[4 * q + 3] = f2_pack(a.w, a.w);
                float4 b = q1[q];
                xB[4 * q + 0] = f2_pack(b.x, b.x);
                xB[4 * q + 1] = f2_pack(b.y, b.y);
                xB[4 * q + 2] = f2_pack(b.z, b.z);
                xB[4 * q + 3] = f2_pack(b.w, b.w);
            }
        }

        unsigned long long yA01 = 0ull, yA23 = 0ull, yB01 = 0ull, yB23 = 0ull;
        int m3 = 0, m2 = 0;
#pragma unroll
        for (int i = 0; i < 16; i++) {
            {
                const ulonglong2 c1v = pc[952 + i];
                yA01 = f2_fma(c1v.x, xA[i], yA01);
                yA23 = f2_fma(c1v.y, xA[i], yA23);
                yB01 = f2_fma(c1v.x, xB[i], yB01);
                yB23 = f2_fma(c1v.y, xB[i], yB23);
            }
#pragma unroll
            for (int j = 0; j <= i; j++) {
                const unsigned long long qA = f2_mul(xA[i], xA[j]);
                const unsigned long long qB = f2_mul(xB[i], xB[j]);
                const ulonglong2 c2v = pc[816 + m2]; m2++;
                unsigned long long sA01 = c2v.x, sA23 = c2v.y;
                unsigned long long sB01 = c2v.x, sB23 = c2v.y;
#pragma unroll
                for (int l = 0; l <= j; l++) {
                    const ulonglong2 c3v = pc[m3]; m3++;
                    sA01 = f2_fma(c3v.x, xA[l], sA01);
                    sA23 = f2_fma(c3v.y, xA[l], sA23);
                    sB01 = f2_fma(c3v.x, xB[l], sB01);
                    sB23 = f2_fma(c3v.y, xB[l], sB23);
                }
                yA01 = f2_fma(sA01, qA, yA01);
                yA23 = f2_fma(sA23, qA, yA23);
                yB01 = f2_fma(sB01, qB, yB01);
                yB23 = f2_fma(sB23, qB, yB23);
            }
        }
        float a0, a1, a2, a3;
        f2_unpack(a0, a1, yA01);
        f2_unpack(a2, a3, yA23);
        *(float4*)(g_y + ((size_t)b0 * 128 + c) * 4) = make_float4(a0, a1, a2, a3);
        if (v1) {
            f2_unpack(a0, a1, yB01);
            f2_unpack(a2, a3, yB23);
            *(float4*)(g_y + ((size_t)b1 * 128 + c) * 4) = make_float4(a0, a1, a2, a3);
        }
    }
}

// ---------------- irrep-wise linear + flatten (transposed weights) ----------------
// grid 512 blocks, 256 threads: 2 nodes/block, cc-loop split across 2 thread halves
__global__ __launch_bounds__(256) void k_lin(float* __restrict__ out) {
    __shared__ float sY[2 * 512];       // 4KB: 2 nodes of y[b][c][oc]
    __shared__ float sP[2 * 4 * 128];   // 4KB: partial sums from half h=1
    const int tid = threadIdx.x;
    const int b0 = blockIdx.x * 2;
    const int n = tid & 127, h = tid >> 7;

    ((float4*)sY)[tid] = ((const float4*)(g_y + (size_t)b0 * 512))[tid];
    __syncthreads();

    float acc[2][4];
#pragma unroll
    for (int bb = 0; bb < 2; bb++)
#pragma unroll
        for (int o = 0; o < 4; o++) acc[bb][o] = 0.f;

    const int c0 = h * 64;
    const float4* w0q = (const float4*)(g_wlT + n * 128 + c0);           // 16 float4, contiguous
    const float4* w1q = (const float4*)(g_wlT + 16384 + n * 128 + c0);
#pragma unroll
    for (int q = 0; q < 16; q++) {
        const float4 w0 = w0q[q];
        const float4 w1 = w1q[q];
#pragma unroll
        for (int t = 0; t < 4; t++) {
            const int cc = c0 + q * 4 + t;
            const float w0s = (&w0.x)[t];
            const float w1s = (&w1.x)[t];
#pragma unroll
            for (int bb = 0; bb < 2; bb++) {
                float4 yv = *(const float4*)(sY + bb * 512 + cc * 4);
                acc[bb][0] = fmaf(yv.x, w0s, acc[bb][0]);
                acc[bb][1] = fmaf(yv.y, w1s, acc[bb][1]);
                acc[bb][2] = fmaf(yv.z, w1s, acc[bb][2]);
                acc[bb][3] = fmaf(yv.w, w1s, acc[bb][3]);
            }
        }
    }

    if (h == 1) {
#pragma unroll
        for (int bb = 0; bb < 2; bb++)
#pragma unroll
            for (int o = 0; o < 4; o++) sP[(bb * 4 + o) * 128 + n] = acc[bb][o];
    }
    __syncthreads();
    if (h == 0) {
        const float scale = 0.08838834764831843f; // 1/sqrt(128)
#pragma unroll
        for (int bb = 0; bb < 2; bb++) {
            float* op = out + (size_t)(b0 + bb) * 512;
            float v0 = (acc[bb][0] + sP[(bb * 4 + 0) * 128 + n]) * scale;
            float v1 = (acc[bb][1] + sP[(bb * 4 + 1) * 128 + n]) * scale;
            float v2 = (acc[bb][2] + sP[(bb * 4 + 2) * 128 + n]) * scale;
            float v3 = (acc[bb][3] + sP[(bb * 4 + 3) * 128 + n]) * scale;
            op[n]               = v0;
            op[128 + n * 3 + 0] = v1;
            op[128 + n * 3 + 1] = v2;
            op[128 + n * 3 + 2] = v3;
        }
    }
}

// ---------------- launch ----------------
extern "C" void kernel_launch(void* const* d_in, const int* in_sizes, int n_in,
                              void* d_out, int out_size) {
    const float* node_feats = (const float*)d_in[0];
    const float* u3_0 = (const float*)d_in[1];
    const float* u3_1 = (const float*)d_in[2];
    const float* u2_0 = (const float*)d_in[3];
    const float* u2_1 = (const float*)d_in[4];
    const float* u1_0 = (const float*)d_in[5];
    const float* u1_1 = (const float*)d_in[6];
    const float* w3   = (const float*)d_in[7];
    const float* w2   = (const float*)d_in[8];
    const float* w1   = (const float*)d_in[9];
    const float* wlin = (const float*)d_in[10];
    const int*   spec = (const int*)d_in[11];
    float* out = (float*)d_out;

    k_prep<<<NM3 + 10, 128>>>(u3_0, u3_1, u2_0, u2_1, spec, wlin);
    k_fold<<<dim3(52, 4), 256>>>(w3, w2, w1, u1_0, u1_1);
    k_main_sym<<<dim3(128, 4), TMS>>>(node_feats);
    k_lin<<<512, 256>>>(out);
}